// round 8
// baseline (speedup 1.0000x reference)
#include <cuda_runtime.h>
#include <cuda_bf16.h>

#define BATCH 1024
#define SEQ   256
#define HALF  128

typedef unsigned long long u64;

__device__ __forceinline__ u64 pack2(float lo, float hi) {
    u64 r; asm("mov.b64 %0, {%1,%2};" : "=l"(r) : "f"(lo), "f"(hi)); return r;
}
__device__ __forceinline__ void unpack2(u64 v, float& lo, float& hi) {
    asm("mov.b64 {%0,%1}, %2;" : "=f"(lo), "=f"(hi) : "l"(v));
}
__device__ __forceinline__ u64 ffma2(u64 a, u64 b, u64 c) {
    u64 d; asm("fma.rn.f32x2 %0, %1, %2, %3;" : "=l"(d) : "l"(a), "l"(b), "l"(c)); return d;
}
__device__ __forceinline__ u64 fmul2(u64 a, u64 b) {
    u64 d; asm("mul.rn.f32x2 %0, %1, %2;" : "=l"(d) : "l"(a), "l"(b)); return d;
}
__device__ __forceinline__ float ex2f(float x) {
    float r; asm("ex2.approx.f32 %0, %1;" : "=f"(r) : "f"(x)); return r;
}

// One CTA per batch, 128 threads, 2 query rows per thread.
// K/V stored PRE-PACKED as f32x2 pairs in SMEM (K pre-scaled by 0.5*log2e),
// so the inner loop is pure LDS.128 + f32x2 FMA + EX2 with no pack movs.
// Reg-capped to 64 (8 CTAs/SM) to fix the R7 occupancy bottleneck.
__global__ __launch_bounds__(HALF, 8) void hybrid_attn_kernel(
    const float* __restrict__ x,
    const float* __restrict__ Wq, const float* __restrict__ Wk, const float* __restrict__ Wv,
    const float* __restrict__ W1, const float* __restrict__ b1,
    const float* __restrict__ W2, const float* __restrict__ b2,
    const float* __restrict__ W3, const float* __restrict__ b3,
    float* __restrict__ out)
{
    __shared__ ulonglong2 sk[SEQ];   // .x = (k0*cs, k1*cs), .y = (k2*cs, k3*cs)
    __shared__ ulonglong2 sv[SEQ];   // .x = (v0, v1),       .y = (v2, v3)
    __shared__ float sWq[16], sWk[16], sWv[16];
    __shared__ float sW1[32], sb1[8], sW2[32], sb2[4], sW3[4], sb3;

    const int tid = threadIdx.x;
    const int b   = blockIdx.x;

    if (tid < 16) { sWq[tid] = Wq[tid]; sWk[tid] = Wk[tid]; sWv[tid] = Wv[tid]; }
    if (tid < 32) { sW1[tid] = W1[tid]; sW2[tid] = W2[tid]; }
    if (tid < 8)  { sb1[tid] = b1[tid]; }
    if (tid < 4)  { sb2[tid] = b2[tid]; sW3[tid] = W3[tid]; }
    if (tid == 0) { sb3 = b3[0]; }

    // Two x rows per thread (overlaps the barrier).
    const float4 xa = reinterpret_cast<const float4*>(x)[b * SEQ + tid];
    const float4 xb = reinterpret_cast<const float4*>(x)[b * SEQ + tid + HALF];

    __syncthreads();   // weights staged before any read

    #define PROJ(W, xv, o0, o1, o2, o3)                                        \
        o0 = xv.x*W[0] + xv.y*W[4] + xv.z*W[8]  + xv.w*W[12];                  \
        o1 = xv.x*W[1] + xv.y*W[5] + xv.z*W[9]  + xv.w*W[13];                  \
        o2 = xv.x*W[2] + xv.y*W[6] + xv.z*W[10] + xv.w*W[14];                  \
        o3 = xv.x*W[3] + xv.y*W[7] + xv.z*W[11] + xv.w*W[15];

    // Softmax scale (0.5) * log2(e), folded into K at store time.
    const float cs = 0.72134752044448170368f;

    float qa0,qa1,qa2,qa3, qb0,qb1,qb2,qb3;
    float t0,t1,t2,t3;

    PROJ(sWq, xa, qa0,qa1,qa2,qa3)
    PROJ(sWq, xb, qb0,qb1,qb2,qb3)

    PROJ(sWk, xa, t0,t1,t2,t3)
    sk[tid]        = make_ulonglong2(pack2(t0*cs, t1*cs), pack2(t2*cs, t3*cs));
    PROJ(sWk, xb, t0,t1,t2,t3)
    sk[tid + HALF] = make_ulonglong2(pack2(t0*cs, t1*cs), pack2(t2*cs, t3*cs));

    PROJ(sWv, xa, t0,t1,t2,t3)
    sv[tid]        = make_ulonglong2(pack2(t0, t1), pack2(t2, t3));
    PROJ(sWv, xb, t0,t1,t2,t3)
    sv[tid + HALF] = make_ulonglong2(pack2(t0, t1), pack2(t2, t3));
    #undef PROJ

    const u64 qa01 = pack2(qa0, qa1), qa23 = pack2(qa2, qa3);
    const u64 qb01 = pack2(qb0, qb1), qb23 = pack2(qb2, qb3);

    __syncthreads();

    u64 accA01 = 0, accA23 = 0, accB01 = 0, accB23 = 0;  // 0ull == (0.0f, 0.0f)
    float lA = 0.0f, lB = 0.0f;

    #pragma unroll 4
    for (int t = 0; t < SEQ; ++t) {
        const ulonglong2 kk = sk[t];   // one LDS.128, pair-aligned
        const ulonglong2 vv = sv[t];   // one LDS.128, pair-aligned

        // row A
        u64 pA = ffma2(qa01, kk.x, fmul2(qa23, kk.y));
        float pA0, pA1; unpack2(pA, pA0, pA1);
        float eA = ex2f(pA0 + pA1);
        // row B
        u64 pB = ffma2(qb01, kk.x, fmul2(qb23, kk.y));
        float pB0, pB1; unpack2(pB, pB0, pB1);
        float eB = ex2f(pB0 + pB1);

        u64 eeA = pack2(eA, eA);
        accA01 = ffma2(eeA, vv.x, accA01);
        accA23 = ffma2(eeA, vv.y, accA23);
        lA += eA;

        u64 eeB = pack2(eB, eB);
        accB01 = ffma2(eeB, vv.x, accB01);
        accB23 = ffma2(eeB, vv.y, accB23);
        lB += eB;
    }

    // MLP head per row: 4 -> 8 (tanh) -> 4 (tanh) -> 1
    #pragma unroll
    for (int r = 0; r < 2; ++r) {
        float a0, a1, a2, a3, l;
        if (r == 0) { unpack2(accA01, a0, a1); unpack2(accA23, a2, a3); l = lA; }
        else        { unpack2(accB01, a0, a1); unpack2(accB23, a2, a3); l = lB; }
        const float inv = 1.0f / l;
        a0 *= inv; a1 *= inv; a2 *= inv; a3 *= inv;

        float h1[8];
        #pragma unroll
        for (int i = 0; i < 8; ++i) {
            float u = a0*sW1[0*8+i] + a1*sW1[1*8+i] + a2*sW1[2*8+i] + a3*sW1[3*8+i] + sb1[i];
            h1[i] = tanhf(u);
        }
        float h2[4];
        #pragma unroll
        for (int i = 0; i < 4; ++i) {
            float u = sb2[i];
            #pragma unroll
            for (int j = 0; j < 8; ++j) u += h1[j] * sW2[j*4+i];
            h2[i] = tanhf(u);
        }
        float o = h2[0]*sW3[0] + h2[1]*sW3[1] + h2[2]*sW3[2] + h2[3]*sW3[3] + sb3;
        out[b * SEQ + tid + r * HALF] = o;
    }
}

extern "C" void kernel_launch(void* const* d_in, const int* in_sizes, int n_in,
                              void* d_out, int out_size) {
    const float* x  = (const float*)d_in[0];
    const float* Wq = (const float*)d_in[1];
    const float* Wk = (const float*)d_in[2];
    const float* Wv = (const float*)d_in[3];
    const float* W1 = (const float*)d_in[4];
    const float* b1 = (const float*)d_in[5];
    const float* W2 = (const float*)d_in[6];
    const float* b2 = (const float*)d_in[7];
    const float* W3 = (const float*)d_in[8];
    const float* b3 = (const float*)d_in[9];
    float* out = (float*)d_out;

    hybrid_attn_kernel<<<BATCH, HALF>>>(x, Wq, Wk, Wv, W1, b1, W2, b2, W3, b3, out);
}